// round 3
// baseline (speedup 1.0000x reference)
#include <cuda_runtime.h>
#include <cuda_bf16.h>
#include <cstdint>

// Problem constants
#define BATCH   2
#define SEQ     2048
#define DMODEL  1024
#define DINNER  2048
#define DSTATE  16
#define DCONV   4
#define MROWS   (BATCH*SEQ)          // 4096

// Scratch (device globals; allocation is forbidden)
__device__ float g_xz[(size_t)MROWS * 2 * DINNER];   // [4096, 4096]  xs_raw | z
__device__ float g_xs[(size_t)MROWS * DINNER];       // post conv+silu
__device__ float g_delta[(size_t)MROWS * DINNER];    // softplus(xs@W_dt+b)
__device__ float g_Bp[(size_t)MROWS * DSTATE];       // (xs@W_x)[:,16:32]
__device__ float g_yg[(size_t)MROWS * DINNER];       // gated scan output

// ---------------------------------------------------------------------------
// SGEMM: C[M,N] = A[M,K] @ B[K,N], all row-major. 128x128 block, 8x8/thread.
// Two-stage pipeline: next k-tile's LDGs issued right after the sync, so they
// overlap with the current tile's 512 FMAs.
// EPI=0: plain store. EPI=1: softplus(v + bias[col]).
// Requires M%128==0, N%128==0, K%16==0.
// ---------------------------------------------------------------------------
template <int EPI>
__global__ __launch_bounds__(256) void sgemm_k(
    const float* __restrict__ A, const float* __restrict__ B,
    float* __restrict__ C, int M, int N, int K, const float* __restrict__ bias)
{
    __shared__ float As[8][128];
    __shared__ float Bs[8][128];

    const int tid = threadIdx.x;
    const int bm = blockIdx.y, bn = blockIdx.x;

    const int arow = tid >> 1;            // 0..127
    const int acol = (tid & 1) << 2;      // 0 or 4
    const int brow = tid >> 5;            // 0..7
    const int bcol = (tid & 31) << 2;     // 0..124

    const int tx = tid & 15, ty = tid >> 4;

    const float* Aptr = A + (size_t)(bm * 128 + arow) * K + acol;
    const float* Bptr = B + (size_t)brow * N + bn * 128 + bcol;

    float acc[8][8];
    #pragma unroll
    for (int i = 0; i < 8; i++)
        #pragma unroll
        for (int j = 0; j < 8; j++) acc[i][j] = 0.f;

    // prologue: fetch tile 0
    float4 av = *(const float4*)Aptr;  Aptr += 8;
    float4 bv = *(const float4*)Bptr;  Bptr += (size_t)8 * N;

    const int ntiles = K / 8;
    for (int t = 0; t < ntiles; t++) {
        As[acol + 0][arow] = av.x;
        As[acol + 1][arow] = av.y;
        As[acol + 2][arow] = av.z;
        As[acol + 3][arow] = av.w;
        *(float4*)&Bs[brow][bcol] = bv;
        __syncthreads();

        // prefetch next tile (overlaps with FMAs below)
        if (t + 1 < ntiles) {
            av = *(const float4*)Aptr;  Aptr += 8;
            bv = *(const float4*)Bptr;  Bptr += (size_t)8 * N;
        }

        #pragma unroll
        for (int k = 0; k < 8; k++) {
            float4 a0 = *(const float4*)&As[k][ty * 4];
            float4 a1 = *(const float4*)&As[k][64 + ty * 4];
            float4 b0 = *(const float4*)&Bs[k][tx * 4];
            float4 b1 = *(const float4*)&Bs[k][64 + tx * 4];
            float a[8] = {a0.x,a0.y,a0.z,a0.w,a1.x,a1.y,a1.z,a1.w};
            float b[8] = {b0.x,b0.y,b0.z,b0.w,b1.x,b1.y,b1.z,b1.w};
            #pragma unroll
            for (int i = 0; i < 8; i++)
                #pragma unroll
                for (int j = 0; j < 8; j++)
                    acc[i][j] = fmaf(a[i], b[j], acc[i][j]);
        }
        __syncthreads();
    }

    #pragma unroll
    for (int i = 0; i < 8; i++) {
        int r = bm * 128 + ((i < 4) ? (ty * 4 + i) : (60 + ty * 4 + i));
        float* crow = C + (size_t)r * N + bn * 128;
        #pragma unroll
        for (int jh = 0; jh < 2; jh++) {
            int c0 = jh * 64 + tx * 4;
            float4 v;
            float vv[4] = {acc[i][jh*4+0], acc[i][jh*4+1], acc[i][jh*4+2], acc[i][jh*4+3]};
            if (EPI == 1) {
                #pragma unroll
                for (int j = 0; j < 4; j++) {
                    float t = vv[j] + bias[bn * 128 + c0 + j];
                    vv[j] = (t > 20.f) ? t : log1pf(__expf(t));
                }
            }
            v.x = vv[0]; v.y = vv[1]; v.z = vv[2]; v.w = vv[3];
            *(float4*)&crow[c0] = v;
        }
    }
}

// ---------------------------------------------------------------------------
// Depthwise causal conv (width 4) + bias + silu.  xz[:, :DINNER] -> xs
// ---------------------------------------------------------------------------
__global__ __launch_bounds__(256) void conv_silu_k(
    const float* __restrict__ xz, const float* __restrict__ cw,
    const float* __restrict__ cb, float* __restrict__ xs)
{
    int idx = blockIdx.x * blockDim.x + threadIdx.x;   // over MROWS*DINNER
    if (idx >= MROWS * DINNER) return;
    int d   = idx & (DINNER - 1);
    int row = idx >> 11;             // b*SEQ + l
    int l   = row & (SEQ - 1);

    float accv = cb[d];
    const float* base = xz + (size_t)row * (2 * DINNER) + d;
    #pragma unroll
    for (int k = 0; k < DCONV; k++) {
        int lk = l + k - (DCONV - 1);
        if (lk >= 0)
            accv = fmaf(cw[d * DCONV + k], base[(ptrdiff_t)(k - (DCONV - 1)) * (2 * DINNER)], accv);
    }
    float e = __expf(-accv);
    xs[idx] = accv / (1.f + e);
}

// ---------------------------------------------------------------------------
// Bp[row, s] = sum_d xs[row,d] * W_x[d, 16+s]   (M=4096, N=16, K=2048)
// Block: 64 rows, 256 threads, K-tiles of 64.
// ---------------------------------------------------------------------------
__global__ __launch_bounds__(256) void bp_k(
    const float* __restrict__ xs, const float* __restrict__ Wx,
    float* __restrict__ Bp)
{
    __shared__ float sx[64][65];     // [row][k]
    __shared__ float sw[64][16];     // [k][col]
    const int tid = threadIdx.x;
    const int row0 = blockIdx.x * 64;
    const int col = tid & 15;
    const int rbase = (tid >> 4) * 4;

    float acc[4] = {0.f, 0.f, 0.f, 0.f};

    for (int k0 = 0; k0 < DINNER; k0 += 64) {
        #pragma unroll
        for (int i = 0; i < 4; i++) {
            int t = tid + i * 256;
            int r = t >> 4;
            int c = (t & 15) << 2;
            float4 v = *(const float4*)&xs[(size_t)(row0 + r) * DINNER + k0 + c];
            sx[r][c + 0] = v.x; sx[r][c + 1] = v.y;
            sx[r][c + 2] = v.z; sx[r][c + 3] = v.w;
        }
        {
            int r = tid >> 2;
            int c = (tid & 3) << 2;
            float4 w = *(const float4*)&Wx[(size_t)(k0 + r) * (2 * DSTATE) + DSTATE + c];
            sw[r][c + 0] = w.x; sw[r][c + 1] = w.y;
            sw[r][c + 2] = w.z; sw[r][c + 3] = w.w;
        }
        __syncthreads();
        #pragma unroll 16
        for (int k = 0; k < 64; k++) {
            float w = sw[k][col];
            #pragma unroll
            for (int i = 0; i < 4; i++)
                acc[i] = fmaf(sx[rbase + i][k], w, acc[i]);
        }
        __syncthreads();
    }
    #pragma unroll
    for (int i = 0; i < 4; i++)
        Bp[(size_t)(row0 + rbase + i) * DSTATE + col] = acc[i];
}

// ---------------------------------------------------------------------------
// Selective scan + gating. 16 lanes per channel (one per state).
// yg[b,l,d] = (sum_s h_s + xs*D[d]) * silu(z[b,l,d])
// Launch: BATCH*DINNER channels * DSTATE lanes = 65536 threads = 256 blocks.
// ---------------------------------------------------------------------------
__global__ __launch_bounds__(256) void scan_k(
    const float* __restrict__ delta, const float* __restrict__ xs,
    const float* __restrict__ Bp, const float* __restrict__ xz,
    const float* __restrict__ A_log, const float* __restrict__ Dp,
    float* __restrict__ yg)
{
    const int tid = threadIdx.x;
    const int half = tid >> 4;                 // channel within block (0..15)
    const int s = tid & 15;                    // state index
    const int ch = blockIdx.x * 16 + half;     // 0 .. BATCH*DINNER-1
    const int b = ch >> 11;                    // DINNER = 2^11
    const int d = ch & (DINNER - 1);

    const float A  = -__expf(A_log[d * DSTATE + s]);
    const float Dv = Dp[d];

    const float* dptr  = delta + (size_t)b * SEQ * DINNER + d;
    const float* xptr  = xs    + (size_t)b * SEQ * DINNER + d;
    const float* bpptr = Bp    + (size_t)b * SEQ * DSTATE + s;
    const float* zptr  = xz    + (size_t)b * SEQ * (2 * DINNER) + DINNER + d;
    float*       optr  = yg    + (size_t)b * SEQ * DINNER + d;

    float h = 0.f;
    for (int l = 0; l < SEQ; l++) {
        float dv  = __ldg(dptr);  dptr += DINNER;
        float xv  = __ldg(xptr);  xptr += DINNER;
        float bpv = __ldg(bpptr); bpptr += DSTATE;

        float dA = __expf(dv * A);
        h = fmaf(dA, h, dv * xv * bpv);

        float v = h;
        v += __shfl_xor_sync(0xffffffffu, v, 1);
        v += __shfl_xor_sync(0xffffffffu, v, 2);
        v += __shfl_xor_sync(0xffffffffu, v, 4);
        v += __shfl_xor_sync(0xffffffffu, v, 8);

        if (s == 0) {
            float zv = __ldg(zptr);
            float sig = zv / (1.f + __expf(-zv));
            *optr = (v + xv * Dv) * sig;
        }
        zptr += 2 * DINNER;
        optr += DINNER;
    }
}

// ---------------------------------------------------------------------------
extern "C" void kernel_launch(void* const* d_in, const int* in_sizes, int n_in,
                              void* d_out, int out_size)
{
    const float* x      = (const float*)d_in[0];
    const float* W_in   = (const float*)d_in[1];
    const float* conv_w = (const float*)d_in[2];
    const float* conv_b = (const float*)d_in[3];
    const float* W_x    = (const float*)d_in[4];
    const float* W_dt   = (const float*)d_in[5];
    const float* b_dt   = (const float*)d_in[6];
    const float* A_log  = (const float*)d_in[7];
    const float* D_par  = (const float*)d_in[8];
    const float* W_out  = (const float*)d_in[9];
    float* out = (float*)d_out;

    float *xz, *xs, *delta, *bp, *yg;
    cudaGetSymbolAddress((void**)&xz,    g_xz);
    cudaGetSymbolAddress((void**)&xs,    g_xs);
    cudaGetSymbolAddress((void**)&delta, g_delta);
    cudaGetSymbolAddress((void**)&bp,    g_Bp);
    cudaGetSymbolAddress((void**)&yg,    g_yg);

    // 1) xz = x @ W_in                       [4096,1024]x[1024,4096]
    sgemm_k<0><<<dim3(2 * DINNER / 128, MROWS / 128), 256>>>(
        x, W_in, xz, MROWS, 2 * DINNER, DMODEL, nullptr);

    // 2) depthwise conv + silu -> xs
    conv_silu_k<<<(MROWS * DINNER + 255) / 256, 256>>>(xz, conv_w, conv_b, xs);

    // 3) delta = softplus(xs @ W_dt + b_dt)  [4096,2048]x[2048,2048]
    sgemm_k<1><<<dim3(DINNER / 128, MROWS / 128), 256>>>(
        xs, W_dt, delta, MROWS, DINNER, DINNER, b_dt);

    // 3b) Bp = (xs @ W_x)[:, 16:32]
    bp_k<<<MROWS / 64, 256>>>(xs, W_x, bp);

    // 4) selective scan + gating -> yg   (BATCH*DINNER*DSTATE threads = 256 blocks)
    scan_k<<<(BATCH * DINNER * DSTATE) / 256, 256>>>(delta, xs, bp, xz, A_log, D_par, yg);

    // 5) out = yg @ W_out                    [4096,2048]x[2048,1024]
    sgemm_k<0><<<dim3(DMODEL / 128, MROWS / 128), 256>>>(
        yg, W_out, out, MROWS, DMODEL, DINNER, nullptr);
}

// round 6
// speedup vs baseline: 1.4002x; 1.4002x over previous
#include <cuda_runtime.h>
#include <cuda_bf16.h>
#include <cstdint>

// Problem constants
#define BATCH   2
#define SEQ     2048
#define DMODEL  1024
#define DINNER  2048
#define DSTATE  16
#define DCONV   4
#define MROWS   (BATCH*SEQ)          // 4096

// Scratch (device globals; allocation is forbidden)
__device__ float g_xz[(size_t)MROWS * 2 * DINNER];   // [4096, 4096]  xs_raw | z
__device__ float g_xs[(size_t)MROWS * DINNER];       // post conv+silu
__device__ float g_delta[(size_t)MROWS * DINNER];    // softplus(xs@W_dt+b)
__device__ float g_Bp[(size_t)MROWS * DSTATE];       // (xs@W_x)[:,16:32]
__device__ float g_yg[(size_t)MROWS * DINNER];       // gated scan output
__device__ float g_WinT[(size_t)(2*DINNER) * DMODEL];  // W_in^T  [4096,1024]
__device__ float g_WdtT[(size_t)DINNER * DINNER];      // W_dt^T  [2048,2048]
__device__ float g_WoutT[(size_t)DMODEL * DINNER];     // W_out^T [1024,2048]

// ---------------------------------------------------------------------------
// fp32 -> tf32 (round to nearest) ; mma.sync tf32 wrapper
// ---------------------------------------------------------------------------
__device__ __forceinline__ uint32_t f2tf32(float f) {
    uint32_t r;
    asm("cvt.rna.tf32.f32 %0, %1;" : "=r"(r) : "f"(f));
    return r;
}

__device__ __forceinline__ void mma_tf32(float c[4],
    uint32_t a0, uint32_t a1, uint32_t a2, uint32_t a3,
    uint32_t b0, uint32_t b1)
{
    asm volatile(
        "mma.sync.aligned.m16n8k8.row.col.f32.tf32.tf32.f32 "
        "{%0,%1,%2,%3}, {%4,%5,%6,%7}, {%8,%9}, {%0,%1,%2,%3};"
        : "+f"(c[0]), "+f"(c[1]), "+f"(c[2]), "+f"(c[3])
        : "r"(a0), "r"(a1), "r"(a2), "r"(a3), "r"(b0), "r"(b1));
}

// ===========================================================================
// TF32 tensor-core GEMM: C[M,N] = A[M,K] @ Bt[N,K]^T   (Bt row-major [N,K])
// CTA tile 128x128, BK=32, 256 threads = 8 warps as 2(M) x 4(N), warp tile
// 64x32, mma m16n8k8. Smem stride 36 words -> conflict-free fragment loads.
// EPI=0 plain, EPI=1 softplus(v + bias[col]).  M%128==0, N%128==0, K%32==0.
// ===========================================================================
#define SSTRIDE 36

template <int EPI>
__global__ void __launch_bounds__(256, 1) gemm_tc(
    const float* __restrict__ A, const float* __restrict__ Bt,
    float* __restrict__ C, int M, int N, int K, const float* __restrict__ bias)
{
    __shared__ uint32_t As[128 * SSTRIDE];
    __shared__ uint32_t Bs[128 * SSTRIDE];

    const int tid = threadIdx.x;
    const int wid = tid >> 5, lane = tid & 31;
    const int g  = lane >> 2;        // 0..7
    const int tg = lane & 3;         // 0..3
    const int wm = wid & 1;          // 0..1  (M slot, 64 rows)
    const int wn = wid >> 1;         // 0..3  (N slot, 32 cols)
    const int bm = blockIdx.y, bn = blockIdx.x;

    const float* Ab = A  + (size_t)(bm * 128) * K;
    const float* Bb = Bt + (size_t)(bn * 128) * K;

    float acc[4][4][4];              // [mi][ni][frag]
    #pragma unroll
    for (int i = 0; i < 4; i++)
        #pragma unroll
        for (int j = 0; j < 4; j++)
            #pragma unroll
            for (int f = 0; f < 4; f++) acc[i][j][f] = 0.f;

    // staging indices: idx = tid + i*256 -> row = idx>>3 (0..127), q = idx&7
    const int nchunk = K / 32;

    // prologue: fetch chunk 0 into registers
    float4 av[4], bv[4];
    #pragma unroll
    for (int i = 0; i < 4; i++) {
        int idx = tid + i * 256;
        int row = idx >> 3, q = idx & 7;
        av[i] = *(const float4*)(Ab + (size_t)row * K + q * 4);
        bv[i] = *(const float4*)(Bb + (size_t)row * K + q * 4);
    }

    for (int c = 0; c < nchunk; c++) {
        // store staged chunk to smem (with tf32 rounding)
        #pragma unroll
        for (int i = 0; i < 4; i++) {
            int idx = tid + i * 256;
            int row = idx >> 3, q = idx & 7;
            uint32_t* pa = &As[row * SSTRIDE + q * 4];
            uint32_t* pb = &Bs[row * SSTRIDE + q * 4];
            uint4 ua, ub;
            ua.x = f2tf32(av[i].x); ua.y = f2tf32(av[i].y);
            ua.z = f2tf32(av[i].z); ua.w = f2tf32(av[i].w);
            ub.x = f2tf32(bv[i].x); ub.y = f2tf32(bv[i].y);
            ub.z = f2tf32(bv[i].z); ub.w = f2tf32(bv[i].w);
            *(uint4*)pa = ua;
            *(uint4*)pb = ub;
        }
        __syncthreads();

        // prefetch next chunk (overlaps with mma below)
        if (c + 1 < nchunk) {
            int k0n = (c + 1) * 32;
            #pragma unroll
            for (int i = 0; i < 4; i++) {
                int idx = tid + i * 256;
                int row = idx >> 3, q = idx & 7;
                av[i] = *(const float4*)(Ab + (size_t)row * K + k0n + q * 4);
                bv[i] = *(const float4*)(Bb + (size_t)row * K + k0n + q * 4);
            }
        }

        // compute: 4 k-steps of 8
        #pragma unroll
        for (int ks = 0; ks < 4; ks++) {
            const int k0 = ks * 8;
            uint32_t af[4][4];   // [mi][frag]
            uint32_t bf[4][2];   // [ni][frag]
            #pragma unroll
            for (int mi = 0; mi < 4; mi++) {
                int mbase = wm * 64 + mi * 16;
                af[mi][0] = As[(mbase + g)     * SSTRIDE + k0 + tg];
                af[mi][1] = As[(mbase + g + 8) * SSTRIDE + k0 + tg];
                af[mi][2] = As[(mbase + g)     * SSTRIDE + k0 + tg + 4];
                af[mi][3] = As[(mbase + g + 8) * SSTRIDE + k0 + tg + 4];
            }
            #pragma unroll
            for (int ni = 0; ni < 4; ni++) {
                int nbase = wn * 32 + ni * 8;
                bf[ni][0] = Bs[(nbase + g) * SSTRIDE + k0 + tg];
                bf[ni][1] = Bs[(nbase + g) * SSTRIDE + k0 + tg + 4];
            }
            #pragma unroll
            for (int mi = 0; mi < 4; mi++)
                #pragma unroll
                for (int ni = 0; ni < 4; ni++)
                    mma_tf32(acc[mi][ni], af[mi][0], af[mi][1], af[mi][2], af[mi][3],
                             bf[ni][0], bf[ni][1]);
        }
        __syncthreads();
    }

    // epilogue: c0=(g,2tg) c1=(g,2tg+1) c2=(g+8,2tg) c3=(g+8,2tg+1)
    #pragma unroll
    for (int mi = 0; mi < 4; mi++) {
        #pragma unroll
        for (int ni = 0; ni < 4; ni++) {
            int row0 = bm * 128 + wm * 64 + mi * 16 + g;
            int col  = bn * 128 + wn * 32 + ni * 8 + 2 * tg;
            float v0 = acc[mi][ni][0], v1 = acc[mi][ni][1];
            float v2 = acc[mi][ni][2], v3 = acc[mi][ni][3];
            if (EPI == 1) {
                float b0 = bias[col], b1 = bias[col + 1];
                v0 += b0; v1 += b1; v2 += b0; v3 += b1;
                v0 = (v0 > 20.f) ? v0 : log1pf(__expf(v0));
                v1 = (v1 > 20.f) ? v1 : log1pf(__expf(v1));
                v2 = (v2 > 20.f) ? v2 : log1pf(__expf(v2));
                v3 = (v3 > 20.f) ? v3 : log1pf(__expf(v3));
            }
            *(float2*)(C + (size_t)row0 * N + col)       = make_float2(v0, v1);
            *(float2*)(C + (size_t)(row0 + 8) * N + col) = make_float2(v2, v3);
        }
    }
}

// ---------------------------------------------------------------------------
// Tiled transpose: out[c][r] = in[r][c].  R, C multiples of 32.
// ---------------------------------------------------------------------------
__global__ __launch_bounds__(256) void transpose_k(
    const float* __restrict__ in, float* __restrict__ out, int R, int C)
{
    __shared__ float t[32][33];
    int bx = blockIdx.x * 32, by = blockIdx.y * 32;
    int x = bx + threadIdx.x;
    #pragma unroll
    for (int i = 0; i < 32; i += 8)
        t[threadIdx.y + i][threadIdx.x] = in[(size_t)(by + threadIdx.y + i) * C + x];
    __syncthreads();
    x = by + threadIdx.x;
    #pragma unroll
    for (int i = 0; i < 32; i += 8)
        out[(size_t)(bx + threadIdx.y + i) * R + x] = t[threadIdx.x][threadIdx.y + i];
}

// ---------------------------------------------------------------------------
// Depthwise causal conv (width 4) + bias + silu.  xz[:, :DINNER] -> xs
// ---------------------------------------------------------------------------
__global__ __launch_bounds__(256) void conv_silu_k(
    const float* __restrict__ xz, const float* __restrict__ cw,
    const float* __restrict__ cb, float* __restrict__ xs)
{
    int idx = blockIdx.x * blockDim.x + threadIdx.x;
    if (idx >= MROWS * DINNER) return;
    int d   = idx & (DINNER - 1);
    int row = idx >> 11;
    int l   = row & (SEQ - 1);

    float accv = cb[d];
    const float* base = xz + (size_t)row * (2 * DINNER) + d;
    #pragma unroll
    for (int k = 0; k < DCONV; k++) {
        int lk = l + k - (DCONV - 1);
        if (lk >= 0)
            accv = fmaf(cw[d * DCONV + k], base[(ptrdiff_t)(k - (DCONV - 1)) * (2 * DINNER)], accv);
    }
    float e = __expf(-accv);
    xs[idx] = accv / (1.f + e);
}

// ---------------------------------------------------------------------------
// Bp[row, s] = sum_d xs[row,d] * W_x[d, 16+s]
// ---------------------------------------------------------------------------
__global__ __launch_bounds__(256) void bp_k(
    const float* __restrict__ xs, const float* __restrict__ Wx,
    float* __restrict__ Bp)
{
    __shared__ float sx[64][65];
    __shared__ float sw[64][16];
    const int tid = threadIdx.x;
    const int row0 = blockIdx.x * 64;
    const int col = tid & 15;
    const int rbase = (tid >> 4) * 4;

    float acc[4] = {0.f, 0.f, 0.f, 0.f};

    for (int k0 = 0; k0 < DINNER; k0 += 64) {
        #pragma unroll
        for (int i = 0; i < 4; i++) {
            int t = tid + i * 256;
            int r = t >> 4;
            int c = (t & 15) << 2;
            float4 v = *(const float4*)&xs[(size_t)(row0 + r) * DINNER + k0 + c];
            sx[r][c + 0] = v.x; sx[r][c + 1] = v.y;
            sx[r][c + 2] = v.z; sx[r][c + 3] = v.w;
        }
        {
            int r = tid >> 2;
            int c = (tid & 3) << 2;
            float4 w = *(const float4*)&Wx[(size_t)(k0 + r) * (2 * DSTATE) + DSTATE + c];
            sw[r][c + 0] = w.x; sw[r][c + 1] = w.y;
            sw[r][c + 2] = w.z; sw[r][c + 3] = w.w;
        }
        __syncthreads();
        #pragma unroll 16
        for (int k = 0; k < 64; k++) {
            float w = sw[k][col];
            #pragma unroll
            for (int i = 0; i < 4; i++)
                acc[i] = fmaf(sx[rbase + i][k], w, acc[i]);
        }
        __syncthreads();
    }
    #pragma unroll
    for (int i = 0; i < 4; i++)
        Bp[(size_t)(row0 + rbase + i) * DSTATE + col] = acc[i];
}

// ---------------------------------------------------------------------------
// Selective scan + gating. 16 lanes per channel (one per state).
// ---------------------------------------------------------------------------
__global__ __launch_bounds__(256) void scan_k(
    const float* __restrict__ delta, const float* __restrict__ xs,
    const float* __restrict__ Bp, const float* __restrict__ xz,
    const float* __restrict__ A_log, const float* __restrict__ Dp,
    float* __restrict__ yg)
{
    const int tid = threadIdx.x;
    const int half = tid >> 4;
    const int s = tid & 15;
    const int ch = blockIdx.x * 16 + half;
    const int b = ch >> 11;
    const int d = ch & (DINNER - 1);

    const float A  = -__expf(A_log[d * DSTATE + s]);
    const float Dv = Dp[d];

    const float* dptr  = delta + (size_t)b * SEQ * DINNER + d;
    const float* xptr  = xs    + (size_t)b * SEQ * DINNER + d;
    const float* bpptr = Bp    + (size_t)b * SEQ * DSTATE + s;
    const float* zptr  = xz    + (size_t)b * SEQ * (2 * DINNER) + DINNER + d;
    float*       optr  = yg    + (size_t)b * SEQ * DINNER + d;

    float h = 0.f;
    for (int l = 0; l < SEQ; l++) {
        float dv  = __ldg(dptr);  dptr += DINNER;
        float xv  = __ldg(xptr);  xptr += DINNER;
        float bpv = __ldg(bpptr); bpptr += DSTATE;

        float dA = __expf(dv * A);
        h = fmaf(dA, h, dv * xv * bpv);

        float v = h;
        v += __shfl_xor_sync(0xffffffffu, v, 1);
        v += __shfl_xor_sync(0xffffffffu, v, 2);
        v += __shfl_xor_sync(0xffffffffu, v, 4);
        v += __shfl_xor_sync(0xffffffffu, v, 8);

        if (s == 0) {
            float zv = __ldg(zptr);
            float sig = zv / (1.f + __expf(-zv));
            *optr = (v + xv * Dv) * sig;
        }
        zptr += 2 * DINNER;
        optr += DINNER;
    }
}

// ---------------------------------------------------------------------------
extern "C" void kernel_launch(void* const* d_in, const int* in_sizes, int n_in,
                              void* d_out, int out_size)
{
    const float* x      = (const float*)d_in[0];
    const float* W_in   = (const float*)d_in[1];
    const float* conv_w = (const float*)d_in[2];
    const float* conv_b = (const float*)d_in[3];
    const float* W_x    = (const float*)d_in[4];
    const float* W_dt   = (const float*)d_in[5];
    const float* b_dt   = (const float*)d_in[6];
    const float* A_log  = (const float*)d_in[7];
    const float* D_par  = (const float*)d_in[8];
    const float* W_out  = (const float*)d_in[9];
    float* out = (float*)d_out;

    float *xz, *xs, *delta, *bp, *yg, *WinT, *WdtT, *WoutT;
    cudaGetSymbolAddress((void**)&xz,    g_xz);
    cudaGetSymbolAddress((void**)&xs,    g_xs);
    cudaGetSymbolAddress((void**)&delta, g_delta);
    cudaGetSymbolAddress((void**)&bp,    g_Bp);
    cudaGetSymbolAddress((void**)&yg,    g_yg);
    cudaGetSymbolAddress((void**)&WinT,  g_WinT);
    cudaGetSymbolAddress((void**)&WdtT,  g_WdtT);
    cudaGetSymbolAddress((void**)&WoutT, g_WoutT);

    // 0) transpose weights to [N,K]
    transpose_k<<<dim3((2*DINNER)/32, DMODEL/32), dim3(32, 8)>>>(W_in,  WinT,  DMODEL, 2*DINNER);
    transpose_k<<<dim3(DINNER/32,     DINNER/32), dim3(32, 8)>>>(W_dt,  WdtT,  DINNER, DINNER);
    transpose_k<<<dim3(DMODEL/32,     DINNER/32), dim3(32, 8)>>>(W_out, WoutT, DINNER, DMODEL);

    // 1) xz = x @ W_in
    gemm_tc<0><<<dim3((2*DINNER)/128, MROWS/128), 256>>>(
        x, WinT, xz, MROWS, 2*DINNER, DMODEL, nullptr);

    // 2) depthwise conv + silu -> xs
    conv_silu_k<<<(MROWS * DINNER + 255) / 256, 256>>>(xz, conv_w, conv_b, xs);

    // 3) delta = softplus(xs @ W_dt + b_dt)
    gemm_tc<1><<<dim3(DINNER/128, MROWS/128), 256>>>(
        xs, WdtT, delta, MROWS, DINNER, DINNER, b_dt);

    // 3b) Bp = (xs @ W_x)[:, 16:32]
    bp_k<<<MROWS / 64, 256>>>(xs, W_x, bp);

    // 4) selective scan + gating -> yg
    scan_k<<<(BATCH * DINNER * DSTATE) / 256, 256>>>(delta, xs, bp, xz, A_log, D_par, yg);

    // 5) out = yg @ W_out
    gemm_tc<0><<<dim3(DMODEL/128, MROWS/128), 256>>>(
        yg, WoutT, out, MROWS, DMODEL, DINNER, nullptr);
}

// round 8
// speedup vs baseline: 2.9410x; 2.1004x over previous
#include <cuda_runtime.h>
#include <cuda_bf16.h>
#include <cstdint>

// Problem constants
#define BATCH   2
#define SEQ     2048
#define DMODEL  1024
#define DINNER  2048
#define DSTATE  16
#define DCONV   4
#define MROWS   (BATCH*SEQ)          // 4096

// Scratch (device globals; allocation is forbidden)
__device__ float g_xz[(size_t)MROWS * 2 * DINNER];   // [4096, 4096]  xs_raw | z
__device__ float g_xs[(size_t)MROWS * DINNER];       // post conv+silu [l,d]
__device__ float g_delta[(size_t)MROWS * DINNER];    // softplus(xs@W_dt+b) [l,d]
__device__ float g_Bp[(size_t)MROWS * DSTATE];       // (xs@W_x)[:,16:32]
__device__ float g_yg[(size_t)MROWS * DINNER];       // gated scan output [l,d]
__device__ float g_WinT[(size_t)(2*DINNER) * DMODEL];  // W_in^T  [4096,1024]
__device__ float g_WdtT[(size_t)DINNER * DINNER];      // W_dt^T  [2048,2048]
__device__ float g_WoutT[(size_t)DMODEL * DINNER];     // W_out^T [1024,2048]
__device__ float g_dT[(size_t)BATCH * DINNER * SEQ];   // delta^T [b,d,l]
__device__ float g_xsT[(size_t)BATCH * DINNER * SEQ];  // xs^T    [b,d,l]
__device__ float g_zT[(size_t)BATCH * DINNER * SEQ];   // z^T     [b,d,l]

// ---------------------------------------------------------------------------
// fp32 -> tf32 (round to nearest) ; mma.sync tf32 wrapper
// ---------------------------------------------------------------------------
__device__ __forceinline__ uint32_t f2tf32(float f) {
    uint32_t r;
    asm("cvt.rna.tf32.f32 %0, %1;" : "=r"(r) : "f"(f));
    return r;
}

__device__ __forceinline__ void mma_tf32(float c[4],
    uint32_t a0, uint32_t a1, uint32_t a2, uint32_t a3,
    uint32_t b0, uint32_t b1)
{
    asm volatile(
        "mma.sync.aligned.m16n8k8.row.col.f32.tf32.tf32.f32 "
        "{%0,%1,%2,%3}, {%4,%5,%6,%7}, {%8,%9}, {%0,%1,%2,%3};"
        : "+f"(c[0]), "+f"(c[1]), "+f"(c[2]), "+f"(c[3])
        : "r"(a0), "r"(a1), "r"(a2), "r"(a3), "r"(b0), "r"(b1));
}

// ===========================================================================
// TF32 tensor-core GEMM: C[M,N] = A[M,K] @ Bt[N,K]^T   (Bt row-major [N,K])
// CTA tile 128x128, BK=32, 256 threads = 8 warps as 2(M) x 4(N), warp tile
// 64x32, mma m16n8k8. Smem stride 36 words -> conflict-free fragment loads.
// EPI=0 plain, EPI=1 softplus(v + bias[col]).  M%128==0, N%128==0, K%32==0.
// ===========================================================================
#define SSTRIDE 36

template <int EPI>
__global__ void __launch_bounds__(256, 1) gemm_tc(
    const float* __restrict__ A, const float* __restrict__ Bt,
    float* __restrict__ C, int M, int N, int K, const float* __restrict__ bias)
{
    __shared__ uint32_t As[128 * SSTRIDE];
    __shared__ uint32_t Bs[128 * SSTRIDE];

    const int tid = threadIdx.x;
    const int wid = tid >> 5, lane = tid & 31;
    const int g  = lane >> 2;        // 0..7
    const int tg = lane & 3;         // 0..3
    const int wm = wid & 1;          // 0..1  (M slot, 64 rows)
    const int wn = wid >> 1;         // 0..3  (N slot, 32 cols)
    const int bm = blockIdx.y, bn = blockIdx.x;

    const float* Ab = A  + (size_t)(bm * 128) * K;
    const float* Bb = Bt + (size_t)(bn * 128) * K;

    float acc[4][4][4];              // [mi][ni][frag]
    #pragma unroll
    for (int i = 0; i < 4; i++)
        #pragma unroll
        for (int j = 0; j < 4; j++)
            #pragma unroll
            for (int f = 0; f < 4; f++) acc[i][j][f] = 0.f;

    const int nchunk = K / 32;

    // prologue: fetch chunk 0 into registers
    float4 av[4], bv[4];
    #pragma unroll
    for (int i = 0; i < 4; i++) {
        int idx = tid + i * 256;
        int row = idx >> 3, q = idx & 7;
        av[i] = *(const float4*)(Ab + (size_t)row * K + q * 4);
        bv[i] = *(const float4*)(Bb + (size_t)row * K + q * 4);
    }

    for (int c = 0; c < nchunk; c++) {
        #pragma unroll
        for (int i = 0; i < 4; i++) {
            int idx = tid + i * 256;
            int row = idx >> 3, q = idx & 7;
            uint32_t* pa = &As[row * SSTRIDE + q * 4];
            uint32_t* pb = &Bs[row * SSTRIDE + q * 4];
            uint4 ua, ub;
            ua.x = f2tf32(av[i].x); ua.y = f2tf32(av[i].y);
            ua.z = f2tf32(av[i].z); ua.w = f2tf32(av[i].w);
            ub.x = f2tf32(bv[i].x); ub.y = f2tf32(bv[i].y);
            ub.z = f2tf32(bv[i].z); ub.w = f2tf32(bv[i].w);
            *(uint4*)pa = ua;
            *(uint4*)pb = ub;
        }
        __syncthreads();

        if (c + 1 < nchunk) {
            int k0n = (c + 1) * 32;
            #pragma unroll
            for (int i = 0; i < 4; i++) {
                int idx = tid + i * 256;
                int row = idx >> 3, q = idx & 7;
                av[i] = *(const float4*)(Ab + (size_t)row * K + k0n + q * 4);
                bv[i] = *(const float4*)(Bb + (size_t)row * K + k0n + q * 4);
            }
        }

        #pragma unroll
        for (int ks = 0; ks < 4; ks++) {
            const int k0 = ks * 8;
            uint32_t af[4][4];
            uint32_t bf[4][2];
            #pragma unroll
            for (int mi = 0; mi < 4; mi++) {
                int mbase = wm * 64 + mi * 16;
                af[mi][0] = As[(mbase + g)     * SSTRIDE + k0 + tg];
                af[mi][1] = As[(mbase + g + 8) * SSTRIDE + k0 + tg];
                af[mi][2] = As[(mbase + g)     * SSTRIDE + k0 + tg + 4];
                af[mi][3] = As[(mbase + g + 8) * SSTRIDE + k0 + tg + 4];
            }
            #pragma unroll
            for (int ni = 0; ni < 4; ni++) {
                int nbase = wn * 32 + ni * 8;
                bf[ni][0] = Bs[(nbase + g) * SSTRIDE + k0 + tg];
                bf[ni][1] = Bs[(nbase + g) * SSTRIDE + k0 + tg + 4];
            }
            #pragma unroll
            for (int mi = 0; mi < 4; mi++)
                #pragma unroll
                for (int ni = 0; ni < 4; ni++)
                    mma_tf32(acc[mi][ni], af[mi][0], af[mi][1], af[mi][2], af[mi][3],
                             bf[ni][0], bf[ni][1]);
        }
        __syncthreads();
    }

    #pragma unroll
    for (int mi = 0; mi < 4; mi++) {
        #pragma unroll
        for (int ni = 0; ni < 4; ni++) {
            int row0 = bm * 128 + wm * 64 + mi * 16 + g;
            int col  = bn * 128 + wn * 32 + ni * 8 + 2 * tg;
            float v0 = acc[mi][ni][0], v1 = acc[mi][ni][1];
            float v2 = acc[mi][ni][2], v3 = acc[mi][ni][3];
            if (EPI == 1) {
                float b0 = bias[col], b1 = bias[col + 1];
                v0 += b0; v1 += b1; v2 += b0; v3 += b1;
                v0 = (v0 > 20.f) ? v0 : log1pf(__expf(v0));
                v1 = (v1 > 20.f) ? v1 : log1pf(__expf(v1));
                v2 = (v2 > 20.f) ? v2 : log1pf(__expf(v2));
                v3 = (v3 > 20.f) ? v3 : log1pf(__expf(v3));
            }
            *(float2*)(C + (size_t)row0 * N + col)       = make_float2(v0, v1);
            *(float2*)(C + (size_t)(row0 + 8) * N + col) = make_float2(v2, v3);
        }
    }
}

// ---------------------------------------------------------------------------
// Tiled transpose: out[c][r] = in[r][c].  R, C multiples of 32.
// ---------------------------------------------------------------------------
__global__ __launch_bounds__(256) void transpose_k(
    const float* __restrict__ in, float* __restrict__ out, int R, int C)
{
    __shared__ float t[32][33];
    int bx = blockIdx.x * 32, by = blockIdx.y * 32;
    int x = bx + threadIdx.x;
    #pragma unroll
    for (int i = 0; i < 32; i += 8)
        t[threadIdx.y + i][threadIdx.x] = in[(size_t)(by + threadIdx.y + i) * C + x];
    __syncthreads();
    x = by + threadIdx.x;
    #pragma unroll
    for (int i = 0; i < 32; i += 8)
        out[(size_t)(bx + threadIdx.y + i) * R + x] = t[threadIdx.x][threadIdx.y + i];
}

// ---------------------------------------------------------------------------
// Strided batched transpose: out[bz][c][r] = in[bz][r][c]
// in rows have stride istride; batches have strides ibstride/obstride.
// ---------------------------------------------------------------------------
__global__ __launch_bounds__(256) void transpose2_k(
    const float* __restrict__ in, float* __restrict__ out,
    int R, int C, int istride, int ostride,
    size_t ibstride, size_t obstride)
{
    __shared__ float t[32][33];
    const float* inb = in + blockIdx.z * ibstride;
    float* outb = out + blockIdx.z * obstride;
    int bx = blockIdx.x * 32, by = blockIdx.y * 32;
    int x = bx + threadIdx.x;
    #pragma unroll
    for (int i = 0; i < 32; i += 8)
        t[threadIdx.y + i][threadIdx.x] = inb[(size_t)(by + threadIdx.y + i) * istride + x];
    __syncthreads();
    x = by + threadIdx.x;
    #pragma unroll
    for (int i = 0; i < 32; i += 8)
        outb[(size_t)(bx + threadIdx.y + i) * ostride + x] = t[threadIdx.x][threadIdx.y + i];
}

// ---------------------------------------------------------------------------
// Depthwise causal conv (width 4) + bias + silu.  xz[:, :DINNER] -> xs
// ---------------------------------------------------------------------------
__global__ __launch_bounds__(256) void conv_silu_k(
    const float* __restrict__ xz, const float* __restrict__ cw,
    const float* __restrict__ cb, float* __restrict__ xs)
{
    int idx = blockIdx.x * blockDim.x + threadIdx.x;
    if (idx >= MROWS * DINNER) return;
    int d   = idx & (DINNER - 1);
    int row = idx >> 11;
    int l   = row & (SEQ - 1);

    float accv = cb[d];
    const float* base = xz + (size_t)row * (2 * DINNER) + d;
    #pragma unroll
    for (int k = 0; k < DCONV; k++) {
        int lk = l + k - (DCONV - 1);
        if (lk >= 0)
            accv = fmaf(cw[d * DCONV + k], base[(ptrdiff_t)(k - (DCONV - 1)) * (2 * DINNER)], accv);
    }
    float e = __expf(-accv);
    xs[idx] = accv / (1.f + e);
}

// ---------------------------------------------------------------------------
// Bp[row, s] = sum_d xs[row,d] * W_x[d, 16+s]
// ---------------------------------------------------------------------------
__global__ __launch_bounds__(256) void bp_k(
    const float* __restrict__ xs, const float* __restrict__ Wx,
    float* __restrict__ Bp)
{
    __shared__ float sx[64][65];
    __shared__ float sw[64][16];
    const int tid = threadIdx.x;
    const int row0 = blockIdx.x * 64;
    const int col = tid & 15;
    const int rbase = (tid >> 4) * 4;

    float acc[4] = {0.f, 0.f, 0.f, 0.f};

    for (int k0 = 0; k0 < DINNER; k0 += 64) {
        #pragma unroll
        for (int i = 0; i < 4; i++) {
            int t = tid + i * 256;
            int r = t >> 4;
            int c = (t & 15) << 2;
            float4 v = *(const float4*)&xs[(size_t)(row0 + r) * DINNER + k0 + c];
            sx[r][c + 0] = v.x; sx[r][c + 1] = v.y;
            sx[r][c + 2] = v.z; sx[r][c + 3] = v.w;
        }
        {
            int r = tid >> 2;
            int c = (tid & 3) << 2;
            float4 w = *(const float4*)&Wx[(size_t)(k0 + r) * (2 * DSTATE) + DSTATE + c];
            sw[r][c + 0] = w.x; sw[r][c + 1] = w.y;
            sw[r][c + 2] = w.z; sw[r][c + 3] = w.w;
        }
        __syncthreads();
        #pragma unroll 16
        for (int k = 0; k < 64; k++) {
            float w = sw[k][col];
            #pragma unroll
            for (int i = 0; i < 4; i++)
                acc[i] = fmaf(sx[rbase + i][k], w, acc[i]);
        }
        __syncthreads();
    }
    #pragma unroll
    for (int i = 0; i < 4; i++)
        Bp[(size_t)(row0 + rbase + i) * DSTATE + col] = acc[i];
}

// ---------------------------------------------------------------------------
// Selective scan v2: channel-major inputs, smem-chunked (16 l-steps / chunk).
// Block = 256 thr = 16 channels x 16 states. Grid = BATCH*DINNER/16 = 256.
// Inputs dT/xsT/zT are [b,d,l] (so row index == global channel id).
// Output yg is [l,d] (token-major) for GEMM3.
// ---------------------------------------------------------------------------
__global__ __launch_bounds__(256) void scan2_k(
    const float* __restrict__ dT, const float* __restrict__ xsT,
    const float* __restrict__ zT, const float* __restrict__ Bp,
    const float* __restrict__ A_log, const float* __restrict__ Dp,
    float* __restrict__ yg)
{
    __shared__ float sd[16][17], sx[16][17], sz[16][17], sy[16][17];
    __shared__ float sb[16][16];      // [l][s]

    const int tid = threadIdx.x;
    const int c = tid >> 4;           // channel within block
    const int s = tid & 15;           // state index
    const int ch0 = blockIdx.x * 16;  // global channel base (never crosses batch)
    const int ch = ch0 + c;
    const int b = ch >> 11;
    const int d = ch & (DINNER - 1);
    const int d0 = ch0 & (DINNER - 1);

    const float A  = -__expf(A_log[d * DSTATE + s]);
    const float Dv = Dp[d];

    // loader role: lch = c (channel), ll = s (l within chunk) -> coalesced in l
    const float* dload = dT  + (size_t)(ch0 + c) * SEQ + s;
    const float* xload = xsT + (size_t)(ch0 + c) * SEQ + s;
    const float* zload = zT  + (size_t)(ch0 + c) * SEQ + s;
    // Bp loader: role (c=l within chunk, s=state) -> coalesced in s
    const float* bload = Bp + (size_t)b * SEQ * DSTATE + (size_t)c * DSTATE + s;

    float h = 0.f;
    for (int l0 = 0; l0 < SEQ; l0 += 16) {
        sd[c][s] = dload[l0];
        sx[c][s] = xload[l0];
        sz[c][s] = zload[l0];
        sb[c][s] = bload[(size_t)l0 * DSTATE];
        __syncthreads();

        #pragma unroll
        for (int li = 0; li < 16; li++) {
            float dv  = sd[c][li];
            float xv  = sx[c][li];
            float bpv = sb[li][s];
            float dA  = __expf(dv * A);
            h = fmaf(dA, h, dv * xv * bpv);

            float v = h;
            v += __shfl_xor_sync(0xffffffffu, v, 1);
            v += __shfl_xor_sync(0xffffffffu, v, 2);
            v += __shfl_xor_sync(0xffffffffu, v, 4);
            v += __shfl_xor_sync(0xffffffffu, v, 8);

            if (s == 0) {
                float zv = sz[c][li];
                float sig = zv / (1.f + __expf(-zv));
                sy[c][li] = (v + xv * Dv) * sig;
            }
        }
        __syncthreads();

        // cooperative coalesced store: sc = tid&15 (channel), sl = tid>>4 (l)
        {
            int sc = tid & 15, sl = tid >> 4;
            yg[(size_t)(b * SEQ + l0 + sl) * DINNER + d0 + sc] = sy[sc][sl];
        }
        __syncthreads();
    }
}

// ---------------------------------------------------------------------------
extern "C" void kernel_launch(void* const* d_in, const int* in_sizes, int n_in,
                              void* d_out, int out_size)
{
    const float* x      = (const float*)d_in[0];
    const float* W_in   = (const float*)d_in[1];
    const float* conv_w = (const float*)d_in[2];
    const float* conv_b = (const float*)d_in[3];
    const float* W_x    = (const float*)d_in[4];
    const float* W_dt   = (const float*)d_in[5];
    const float* b_dt   = (const float*)d_in[6];
    const float* A_log  = (const float*)d_in[7];
    const float* D_par  = (const float*)d_in[8];
    const float* W_out  = (const float*)d_in[9];
    float* out = (float*)d_out;

    float *xz, *xs, *delta, *bp, *yg, *WinT, *WdtT, *WoutT, *dT, *xsT, *zT;
    cudaGetSymbolAddress((void**)&xz,    g_xz);
    cudaGetSymbolAddress((void**)&xs,    g_xs);
    cudaGetSymbolAddress((void**)&delta, g_delta);
    cudaGetSymbolAddress((void**)&bp,    g_Bp);
    cudaGetSymbolAddress((void**)&yg,    g_yg);
    cudaGetSymbolAddress((void**)&WinT,  g_WinT);
    cudaGetSymbolAddress((void**)&WdtT,  g_WdtT);
    cudaGetSymbolAddress((void**)&WoutT, g_WoutT);
    cudaGetSymbolAddress((void**)&dT,    g_dT);
    cudaGetSymbolAddress((void**)&xsT,   g_xsT);
    cudaGetSymbolAddress((void**)&zT,    g_zT);

    // 0) transpose weights to [N,K]
    transpose_k<<<dim3((2*DINNER)/32, DMODEL/32), dim3(32, 8)>>>(W_in,  WinT,  DMODEL, 2*DINNER);
    transpose_k<<<dim3(DINNER/32,     DINNER/32), dim3(32, 8)>>>(W_dt,  WdtT,  DINNER, DINNER);
    transpose_k<<<dim3(DMODEL/32,     DINNER/32), dim3(32, 8)>>>(W_out, WoutT, DINNER, DMODEL);

    // 1) xz = x @ W_in
    gemm_tc<0><<<dim3((2*DINNER)/128, MROWS/128), 256>>>(
        x, WinT, xz, MROWS, 2*DINNER, DMODEL, nullptr);

    // 1b) z^T : [b,l,d] slice of xz -> [b,d,l]
    transpose2_k<<<dim3(DINNER/32, SEQ/32, BATCH), dim3(32, 8)>>>(
        xz + DINNER, zT, SEQ, DINNER, 2*DINNER, SEQ,
        (size_t)SEQ * 2 * DINNER, (size_t)DINNER * SEQ);

    // 2) depthwise conv + silu -> xs [l,d]
    conv_silu_k<<<(MROWS * DINNER + 255) / 256, 256>>>(xz, conv_w, conv_b, xs);

    // 2b) xs^T -> [b,d,l]
    transpose2_k<<<dim3(DINNER/32, SEQ/32, BATCH), dim3(32, 8)>>>(
        xs, xsT, SEQ, DINNER, DINNER, SEQ,
        (size_t)SEQ * DINNER, (size_t)DINNER * SEQ);

    // 3) delta = softplus(xs @ W_dt + b_dt)   [l,d]
    gemm_tc<1><<<dim3(DINNER/128, MROWS/128), 256>>>(
        xs, WdtT, delta, MROWS, DINNER, DINNER, b_dt);

    // 3b) delta^T -> [b,d,l]
    transpose2_k<<<dim3(DINNER/32, SEQ/32, BATCH), dim3(32, 8)>>>(
        delta, dT, SEQ, DINNER, DINNER, SEQ,
        (size_t)SEQ * DINNER, (size_t)DINNER * SEQ);

    // 3c) Bp = (xs @ W_x)[:, 16:32]
    bp_k<<<MROWS / 64, 256>>>(xs, W_x, bp);

    // 4) selective scan + gating -> yg [l,d]
    scan2_k<<<(BATCH * DINNER) / 16, 256>>>(dT, xsT, zT, bp, A_log, D_par, yg);

    // 5) out = yg @ W_out
    gemm_tc<0><<<dim3(DMODEL/128, MROWS/128), 256>>>(
        yg, WoutT, out, MROWS, DMODEL, DINNER, nullptr);
}

// round 10
// speedup vs baseline: 3.0183x; 1.0263x over previous
#include <cuda_runtime.h>
#include <cuda_bf16.h>
#include <cstdint>

// Problem constants
#define BATCH   2
#define SEQ     2048
#define DMODEL  1024
#define DINNER  2048
#define DSTATE  16
#define DCONV   4
#define MROWS   (BATCH*SEQ)          // 4096

// Scratch (device globals; allocation is forbidden)
__device__ float g_xraw[(size_t)MROWS * DINNER];     // pre-conv xs  [l,d]
__device__ float g_xs[(size_t)MROWS * DINNER];       // post conv+silu [l,d]
__device__ float g_Bp[(size_t)MROWS * DSTATE];       // (xs@W_x)[:,16:32]
__device__ float g_yg[(size_t)MROWS * DINNER];       // gated scan output [l,d]
__device__ float g_WinT[(size_t)(2*DINNER) * DMODEL];  // W_in^T  [4096,1024]
__device__ float g_WdtT[(size_t)DINNER * DINNER];      // W_dt^T  [2048,2048]
__device__ float g_WoutT[(size_t)DMODEL * DINNER];     // W_out^T [1024,2048]
__device__ float g_dT[(size_t)BATCH * DINNER * SEQ];   // delta^T [b,d,l]
__device__ float g_xsT[(size_t)BATCH * DINNER * SEQ];  // xs^T    [b,d,l]
__device__ float g_zT[(size_t)BATCH * DINNER * SEQ];   // z^T     [b,d,l]

// ---------------------------------------------------------------------------
__device__ __forceinline__ uint32_t f2tf32(float f) {
    uint32_t r;
    asm("cvt.rna.tf32.f32 %0, %1;" : "=r"(r) : "f"(f));
    return r;
}

__device__ __forceinline__ void mma_tf32(float c[4],
    uint32_t a0, uint32_t a1, uint32_t a2, uint32_t a3,
    uint32_t b0, uint32_t b1)
{
    asm volatile(
        "mma.sync.aligned.m16n8k8.row.col.f32.tf32.tf32.f32 "
        "{%0,%1,%2,%3}, {%4,%5,%6,%7}, {%8,%9}, {%0,%1,%2,%3};"
        : "+f"(c[0]), "+f"(c[1]), "+f"(c[2]), "+f"(c[3])
        : "r"(a0), "r"(a1), "r"(a2), "r"(a3), "r"(b0), "r"(b1));
}

// ===========================================================================
// TF32 tensor-core GEMM with double-buffered smem and fused epilogues.
// C[M,N] = A[M,K] @ Bt[N,K]^T.  CTA tile 128x128, BK=32, 8 warps 2(M)x4(N).
// MODE 0: plain write to C (ldc).
// MODE 2: split (GEMM1): bn<16 -> plain write col bn*128 into C (ldc=2048);
//         bn>=16 -> transposed write of tile into CT as [b, d, l] (zT).
// MODE 3: softplus(v + bias[col]) then transposed write into CT (dT).
// M%128==0, N%128==0, K%32==0. Rows of a tile never straddle a batch.
// ===========================================================================
#define SSTRIDE 36
#define GT_SMEM (2 * 2 * 128 * SSTRIDE * 4)   // 73728 bytes

template <int MODE>
__global__ void __launch_bounds__(256, 1) gemm_tc(
    const float* __restrict__ A, const float* __restrict__ Bt,
    float* __restrict__ C, float* __restrict__ CT,
    int M, int N, int K, int ldc, const float* __restrict__ bias)
{
    extern __shared__ uint32_t sbuf[];   // [2][2][128*SSTRIDE]

    const int tid = threadIdx.x;
    const int wid = tid >> 5, lane = tid & 31;
    const int g  = lane >> 2;        // 0..7
    const int tg = lane & 3;         // 0..3
    const int wm = wid & 1;          // M slot (64 rows)
    const int wn = wid >> 1;         // N slot (32 cols)
    const int bm = blockIdx.y, bn = blockIdx.x;

    const float* Ab = A  + (size_t)(bm * 128) * K;
    const float* Bb = Bt + (size_t)(bn * 128) * K;

    float acc[4][4][4];
    #pragma unroll
    for (int i = 0; i < 4; i++)
        #pragma unroll
        for (int j = 0; j < 4; j++)
            #pragma unroll
            for (int f = 0; f < 4; f++) acc[i][j][f] = 0.f;

    const int nchunk = K / 32;

    float4 av[4], bv[4];
    // G2R chunk 0
    #pragma unroll
    for (int i = 0; i < 4; i++) {
        int idx = tid + i * 256;
        int row = idx >> 3, q = idx & 7;
        av[i] = *(const float4*)(Ab + (size_t)row * K + q * 4);
        bv[i] = *(const float4*)(Bb + (size_t)row * K + q * 4);
    }
    // R2S chunk 0 -> buf 0
    #pragma unroll
    for (int i = 0; i < 4; i++) {
        int idx = tid + i * 256;
        int row = idx >> 3, q = idx & 7;
        uint32_t* pa = &sbuf[row * SSTRIDE + q * 4];
        uint32_t* pb = &sbuf[128 * SSTRIDE + row * SSTRIDE + q * 4];
        uint4 ua, ub;
        ua.x = f2tf32(av[i].x); ua.y = f2tf32(av[i].y);
        ua.z = f2tf32(av[i].z); ua.w = f2tf32(av[i].w);
        ub.x = f2tf32(bv[i].x); ub.y = f2tf32(bv[i].y);
        ub.z = f2tf32(bv[i].z); ub.w = f2tf32(bv[i].w);
        *(uint4*)pa = ua;
        *(uint4*)pb = ub;
    }
    // G2R chunk 1
    if (nchunk > 1) {
        #pragma unroll
        for (int i = 0; i < 4; i++) {
            int idx = tid + i * 256;
            int row = idx >> 3, q = idx & 7;
            av[i] = *(const float4*)(Ab + (size_t)row * K + 32 + q * 4);
            bv[i] = *(const float4*)(Bb + (size_t)row * K + 32 + q * 4);
        }
    }
    __syncthreads();

    for (int c = 0; c < nchunk; c++) {
        // R2S chunk c+1 into buf (c+1)&1  (readers of that buf finished at sync of c-1)
        if (c + 1 < nchunk) {
            uint32_t* base = sbuf + ((c + 1) & 1) * (2 * 128 * SSTRIDE);
            #pragma unroll
            for (int i = 0; i < 4; i++) {
                int idx = tid + i * 256;
                int row = idx >> 3, q = idx & 7;
                uint4 ua, ub;
                ua.x = f2tf32(av[i].x); ua.y = f2tf32(av[i].y);
                ua.z = f2tf32(av[i].z); ua.w = f2tf32(av[i].w);
                ub.x = f2tf32(bv[i].x); ub.y = f2tf32(bv[i].y);
                ub.z = f2tf32(bv[i].z); ub.w = f2tf32(bv[i].w);
                *(uint4*)&base[row * SSTRIDE + q * 4] = ua;
                *(uint4*)&base[128 * SSTRIDE + row * SSTRIDE + q * 4] = ub;
            }
        }
        // G2R chunk c+2
        if (c + 2 < nchunk) {
            int k0n = (c + 2) * 32;
            #pragma unroll
            for (int i = 0; i < 4; i++) {
                int idx = tid + i * 256;
                int row = idx >> 3, q = idx & 7;
                av[i] = *(const float4*)(Ab + (size_t)row * K + k0n + q * 4);
                bv[i] = *(const float4*)(Bb + (size_t)row * K + k0n + q * 4);
            }
        }
        // compute chunk c from buf c&1
        const uint32_t* As = sbuf + (c & 1) * (2 * 128 * SSTRIDE);
        const uint32_t* Bs = As + 128 * SSTRIDE;
        #pragma unroll
        for (int ks = 0; ks < 4; ks++) {
            const int k0 = ks * 8;
            uint32_t af[4][4];
            uint32_t bf[4][2];
            #pragma unroll
            for (int mi = 0; mi < 4; mi++) {
                int mbase = wm * 64 + mi * 16;
                af[mi][0] = As[(mbase + g)     * SSTRIDE + k0 + tg];
                af[mi][1] = As[(mbase + g + 8) * SSTRIDE + k0 + tg];
                af[mi][2] = As[(mbase + g)     * SSTRIDE + k0 + tg + 4];
                af[mi][3] = As[(mbase + g + 8) * SSTRIDE + k0 + tg + 4];
            }
            #pragma unroll
            for (int ni = 0; ni < 4; ni++) {
                int nbase = wn * 32 + ni * 8;
                bf[ni][0] = Bs[(nbase + g) * SSTRIDE + k0 + tg];
                bf[ni][1] = Bs[(nbase + g) * SSTRIDE + k0 + tg + 4];
            }
            #pragma unroll
            for (int mi = 0; mi < 4; mi++)
                #pragma unroll
                for (int ni = 0; ni < 4; ni++)
                    mma_tf32(acc[mi][ni], af[mi][0], af[mi][1], af[mi][2], af[mi][3],
                             bf[ni][0], bf[ni][1]);
        }
        __syncthreads();
    }

    const bool trans = (MODE == 3) || (MODE == 2 && bn >= 16);

    if (!trans) {
        // plain write (MODE 0, or MODE 2 with bn<16)
        #pragma unroll
        for (int mi = 0; mi < 4; mi++) {
            #pragma unroll
            for (int ni = 0; ni < 4; ni++) {
                int row0 = bm * 128 + wm * 64 + mi * 16 + g;
                int col  = bn * 128 + wn * 32 + ni * 8 + 2 * tg;
                *(float2*)(C + (size_t)row0 * ldc + col) =
                    make_float2(acc[mi][ni][0], acc[mi][ni][1]);
                *(float2*)(C + (size_t)(row0 + 8) * ldc + col) =
                    make_float2(acc[mi][ni][2], acc[mi][ni][3]);
            }
        }
    } else {
        // transposed write via smem staging: st[128 d][132] of l values
        float* st = (float*)sbuf;
        const int d0 = (MODE == 2) ? (bn - 16) * 128 : bn * 128;
        const int bz = bm >> 4;              // SEQ/128 = 16 tiles per batch
        const int l0 = (bm & 15) * 128;
        #pragma unroll
        for (int mi = 0; mi < 4; mi++) {
            #pragma unroll
            for (int ni = 0; ni < 4; ni++) {
                int rl = wm * 64 + mi * 16 + g;
                int cl = wn * 32 + ni * 8 + 2 * tg;
                float v0 = acc[mi][ni][0], v1 = acc[mi][ni][1];
                float v2 = acc[mi][ni][2], v3 = acc[mi][ni][3];
                if (MODE == 3) {
                    int col = bn * 128 + cl;
                    float b0 = bias[col], b1 = bias[col + 1];
                    v0 += b0; v1 += b1; v2 += b0; v3 += b1;
                    v0 = (v0 > 20.f) ? v0 : log1pf(__expf(v0));
                    v1 = (v1 > 20.f) ? v1 : log1pf(__expf(v1));
                    v2 = (v2 > 20.f) ? v2 : log1pf(__expf(v2));
                    v3 = (v3 > 20.f) ? v3 : log1pf(__expf(v3));
                }
                st[(cl)     * 132 + rl]     = v0;
                st[(cl + 1) * 132 + rl]     = v1;
                st[(cl)     * 132 + rl + 8] = v2;
                st[(cl + 1) * 132 + rl + 8] = v3;
            }
        }
        __syncthreads();
        #pragma unroll
        for (int i = 0; i < 16; i++) {
            int idx = tid + i * 256;       // 0..4095
            int dl = idx >> 5;             // 0..127
            int c4 = idx & 31;
            float4 v = *(float4*)&st[dl * 132 + c4 * 4];
            *(float4*)&CT[((size_t)bz * DINNER + d0 + dl) * SEQ + l0 + c4 * 4] = v;
        }
    }
}

// ---------------------------------------------------------------------------
// Tiled transpose for weights: out[c][r] = in[r][c].
// ---------------------------------------------------------------------------
__global__ __launch_bounds__(256) void transpose_k(
    const float* __restrict__ in, float* __restrict__ out, int R, int C)
{
    __shared__ float t[32][33];
    int bx = blockIdx.x * 32, by = blockIdx.y * 32;
    int x = bx + threadIdx.x;
    #pragma unroll
    for (int i = 0; i < 32; i += 8)
        t[threadIdx.y + i][threadIdx.x] = in[(size_t)(by + threadIdx.y + i) * C + x];
    __syncthreads();
    x = by + threadIdx.x;
    #pragma unroll
    for (int i = 0; i < 32; i += 8)
        out[(size_t)(bx + threadIdx.y + i) * R + x] = t[threadIdx.x][threadIdx.y + i];
}

// ---------------------------------------------------------------------------
// Tiled depthwise causal conv (width 4) + bias + silu.
// Reads xraw [l,d] (compact, ld=DINNER). Writes xs [l,d] and xsT [b,d,l].
// Grid (DINNER/32, SEQ/32, BATCH), block (32,8).
// ---------------------------------------------------------------------------
__global__ __launch_bounds__(256) void conv_t(
    const float* __restrict__ xraw, const float* __restrict__ cw,
    const float* __restrict__ cb, float* __restrict__ xs,
    float* __restrict__ xsT)
{
    __shared__ float sxin[35][33];
    __shared__ float sy[32][33];
    const int tx = threadIdx.x, ty = threadIdx.y;
    const int d0 = blockIdx.x * 32, l0 = blockIdx.y * 32, b = blockIdx.z;

    #pragma unroll
    for (int i = 0; i < 5; i++) {
        int r = ty + i * 8;
        if (r < 35) {
            int l = l0 + r - 3;
            float v = (l >= 0) ? xraw[((size_t)(b * SEQ + l)) * DINNER + d0 + tx] : 0.f;
            sxin[r][tx] = v;
        }
    }
    __syncthreads();

    const int d = d0 + tx;
    const float w0 = cw[d * 4 + 0], w1 = cw[d * 4 + 1];
    const float w2 = cw[d * 4 + 2], w3 = cw[d * 4 + 3];
    const float bb = cb[d];

    #pragma unroll
    for (int i = 0; i < 4; i++) {
        int r = ty + i * 8;
        float a = bb;
        a = fmaf(w0, sxin[r][tx],     a);
        a = fmaf(w1, sxin[r + 1][tx], a);
        a = fmaf(w2, sxin[r + 2][tx], a);
        a = fmaf(w3, sxin[r + 3][tx], a);
        float val = a / (1.f + __expf(-a));
        sy[r][tx] = val;
        xs[((size_t)(b * SEQ + l0 + r)) * DINNER + d] = val;
    }
    __syncthreads();

    #pragma unroll
    for (int i = 0; i < 4; i++) {
        int dl = ty + i * 8;
        xsT[((size_t)(b * DINNER + d0 + dl)) * SEQ + l0 + tx] = sy[tx][dl];
    }
}

// ---------------------------------------------------------------------------
// Bp[row, s] = sum_d xs[row,d] * W_x[d, 16+s].  32 rows/block, grid 128.
// ---------------------------------------------------------------------------
__global__ __launch_bounds__(256) void bp_k(
    const float* __restrict__ xs, const float* __restrict__ Wx,
    float* __restrict__ Bp)
{
    __shared__ float sx[32][65];
    __shared__ float sw[64][16];
    const int tid = threadIdx.x;
    const int row0 = blockIdx.x * 32;
    const int col = tid & 15;
    const int rbase = (tid >> 4) * 2;

    float acc[2] = {0.f, 0.f};

    for (int k0 = 0; k0 < DINNER; k0 += 64) {
        #pragma unroll
        for (int i = 0; i < 2; i++) {
            int t = tid + i * 256;
            int r = t >> 4;
            int c = (t & 15) << 2;
            float4 v = *(const float4*)&xs[(size_t)(row0 + r) * DINNER + k0 + c];
            sx[r][c + 0] = v.x; sx[r][c + 1] = v.y;
            sx[r][c + 2] = v.z; sx[r][c + 3] = v.w;
        }
        {
            int r = tid >> 2;
            int c = (tid & 3) << 2;
            float4 w = *(const float4*)&Wx[(size_t)(k0 + r) * (2 * DSTATE) + DSTATE + c];
            sw[r][c + 0] = w.x; sw[r][c + 1] = w.y;
            sw[r][c + 2] = w.z; sw[r][c + 3] = w.w;
        }
        __syncthreads();
        #pragma unroll 16
        for (int k = 0; k < 64; k++) {
            float w = sw[k][col];
            acc[0] = fmaf(sx[rbase + 0][k], w, acc[0]);
            acc[1] = fmaf(sx[rbase + 1][k], w, acc[1]);
        }
        __syncthreads();
    }
    Bp[(size_t)(row0 + rbase + 0) * DSTATE + col] = acc[0];
    Bp[(size_t)(row0 + rbase + 1) * DSTATE + col] = acc[1];
}

// ---------------------------------------------------------------------------
// Selective scan v2 (unchanged from R8): channel-major inputs, 16-step chunks.
// ---------------------------------------------------------------------------
__global__ __launch_bounds__(256) void scan2_k(
    const float* __restrict__ dT, const float* __restrict__ xsT,
    const float* __restrict__ zT, const float* __restrict__ Bp,
    const float* __restrict__ A_log, const float* __restrict__ Dp,
    float* __restrict__ yg)
{
    __shared__ float sd[16][17], sx[16][17], sz[16][17], sy[16][17];
    __shared__ float sb[16][16];

    const int tid = threadIdx.x;
    const int c = tid >> 4;
    const int s = tid & 15;
    const int ch0 = blockIdx.x * 16;
    const int ch = ch0 + c;
    const int b = ch >> 11;
    const int d = ch & (DINNER - 1);
    const int d0 = ch0 & (DINNER - 1);

    const float A  = -__expf(A_log[d * DSTATE + s]);
    const float Dv = Dp[d];

    const float* dload = dT  + (size_t)(ch0 + c) * SEQ + s;
    const float* xload = xsT + (size_t)(ch0 + c) * SEQ + s;
    const float* zload = zT  + (size_t)(ch0 + c) * SEQ + s;
    const float* bload = Bp + (size_t)b * SEQ * DSTATE + (size_t)c * DSTATE + s;

    float h = 0.f;
    for (int l0 = 0; l0 < SEQ; l0 += 16) {
        sd[c][s] = dload[l0];
        sx[c][s] = xload[l0];
        sz[c][s] = zload[l0];
        sb[c][s] = bload[(size_t)l0 * DSTATE];
        __syncthreads();

        #pragma unroll
        for (int li = 0; li < 16; li++) {
            float dv  = sd[c][li];
            float xv  = sx[c][li];
            float bpv = sb[li][s];
            float dA  = __expf(dv * A);
            h = fmaf(dA, h, dv * xv * bpv);

            float v = h;
            v += __shfl_xor_sync(0xffffffffu, v, 1);
            v += __shfl_xor_sync(0xffffffffu, v, 2);
            v += __shfl_xor_sync(0xffffffffu, v, 4);
            v += __shfl_xor_sync(0xffffffffu, v, 8);

            if (s == 0) {
                float zv = sz[c][li];
                float sig = zv / (1.f + __expf(-zv));
                sy[c][li] = (v + xv * Dv) * sig;
            }
        }
        __syncthreads();

        {
            int sc = tid & 15, sl = tid >> 4;
            yg[(size_t)(b * SEQ + l0 + sl) * DINNER + d0 + sc] = sy[sc][sl];
        }
        __syncthreads();
    }
}

// ---------------------------------------------------------------------------
extern "C" void kernel_launch(void* const* d_in, const int* in_sizes, int n_in,
                              void* d_out, int out_size)
{
    const float* x      = (const float*)d_in[0];
    const float* W_in   = (const float*)d_in[1];
    const float* conv_w = (const float*)d_in[2];
    const float* conv_b = (const float*)d_in[3];
    const float* W_x    = (const float*)d_in[4];
    const float* W_dt   = (const float*)d_in[5];
    const float* b_dt   = (const float*)d_in[6];
    const float* A_log  = (const float*)d_in[7];
    const float* D_par  = (const float*)d_in[8];
    const float* W_out  = (const float*)d_in[9];
    float* out = (float*)d_out;

    float *xraw, *xs, *bp, *yg, *WinT, *WdtT, *WoutT, *dT, *xsT, *zT;
    cudaGetSymbolAddress((void**)&xraw,  g_xraw);
    cudaGetSymbolAddress((void**)&xs,    g_xs);
    cudaGetSymbolAddress((void**)&bp,    g_Bp);
    cudaGetSymbolAddress((void**)&yg,    g_yg);
    cudaGetSymbolAddress((void**)&WinT,  g_WinT);
    cudaGetSymbolAddress((void**)&WdtT,  g_WdtT);
    cudaGetSymbolAddress((void**)&WoutT, g_WoutT);
    cudaGetSymbolAddress((void**)&dT,    g_dT);
    cudaGetSymbolAddress((void**)&xsT,   g_xsT);
    cudaGetSymbolAddress((void**)&zT,    g_zT);

    cudaFuncSetAttribute((const void*)gemm_tc<0>,
                         cudaFuncAttributeMaxDynamicSharedMemorySize, GT_SMEM);
    cudaFuncSetAttribute((const void*)gemm_tc<2>,
                         cudaFuncAttributeMaxDynamicSharedMemorySize, GT_SMEM);
    cudaFuncSetAttribute((const void*)gemm_tc<3>,
                         cudaFuncAttributeMaxDynamicSharedMemorySize, GT_SMEM);

    // 0) transpose weights to [N,K]
    transpose_k<<<dim3((2*DINNER)/32, DMODEL/32), dim3(32, 8)>>>(W_in,  WinT,  DMODEL, 2*DINNER);
    transpose_k<<<dim3(DINNER/32,     DINNER/32), dim3(32, 8)>>>(W_dt,  WdtT,  DINNER, DINNER);
    transpose_k<<<dim3(DMODEL/32,     DINNER/32), dim3(32, 8)>>>(W_out, WoutT, DINNER, DMODEL);

    // 1) x @ W_in: cols 0..2047 -> xraw [l,d]; cols 2048..4095 -> zT [b,d,l]
    gemm_tc<2><<<dim3(32, MROWS/128), 256, GT_SMEM>>>(
        x, WinT, xraw, zT, MROWS, 2*DINNER, DMODEL, DINNER, nullptr);

    // 2) tiled conv+silu -> xs [l,d] and xsT [b,d,l]
    conv_t<<<dim3(DINNER/32, SEQ/32, BATCH), dim3(32, 8)>>>(xraw, conv_w, conv_b, xs, xsT);

    // 3) softplus(xs @ W_dt + b_dt) -> dT [b,d,l] (transposed-only output)
    gemm_tc<3><<<dim3(16, MROWS/128), 256, GT_SMEM>>>(
        xs, WdtT, nullptr, dT, MROWS, DINNER, DINNER, DINNER, b_dt);

    // 3b) Bp = (xs @ W_x)[:, 16:32]
    bp_k<<<MROWS / 32, 256>>>(xs, W_x, bp);

    // 4) selective scan + gating -> yg [l,d]
    scan2_k<<<(BATCH * DINNER) / 16, 256>>>(dT, xsT, zT, bp, A_log, D_par, yg);

    // 5) out = yg @ W_out
    gemm_tc<0><<<dim3(DMODEL/128, MROWS/128), 256, GT_SMEM>>>(
        yg, WoutT, out, nullptr, MROWS, DMODEL, DINNER, DMODEL, nullptr);
}